// round 14
// baseline (speedup 1.0000x reference)
#include <cuda_runtime.h>
#include <cstdint>

// Quantizer: per-row symmetric int4 quant + nibble pack. x: [8192, 4096] fp32.
// Output = concat(packed, scales) upcast to fp32:
//   out[0 .. N*2048)       fp32 value of each packed signed byte
//   out[N*2048 .. +N)      fp32 per-row scale (absmax / 7)
//
// FINAL (converged, best measured bench 32.768us / kernel ~27us):
// 1 row/CTA, 256T, paired input mapping -> 2x STG.128, streaming hints,
// warp-shuffle reduce, pure-FP pack path (bit-identical to int path).
// Measured DRAM traffic (~160MB) / achieved BW (~5.9TB/s) == kernel time:
// at the mixed-stream HBM ceiling. All structural alternatives measured
// neutral or worse across R4-R13 (row fusion, wider CTAs, write-through,
// default caching, barrier amortization, int pack path).

#define H 4096
#define HP (H / 2)
#define THREADS 256
// thread t owns input float4s {2t, 2t+1, 512+2t, 512+2t+1} (16 floats),
// emitting output float4s {t, 256+t} (8 packed-byte floats).

__device__ __forceinline__ float qclamp(float v, float inv) {
    // round-to-nearest-even then clip to [-8, 7]; exact small-int fp32 math
    return fmaxf(fminf(rintf(v * inv), 7.0f), -8.0f);
}

__device__ __forceinline__ float pack2(float a, float b, float inv) {
    const float q0 = qclamp(a, inv);                 // low nibble (even col)
    const float q1 = qclamp(b, inv);                 // high nibble (odd col)
    const float lo = (q0 < 0.0f) ? q0 + 16.0f : q0;  // q0 & 0xF as a value
    return fmaf(q1, 16.0f, lo);                      // signed byte value
}

__device__ __forceinline__ float amax4(float4 v) {
    return fmaxf(fmaxf(fabsf(v.x), fabsf(v.y)), fmaxf(fabsf(v.z), fabsf(v.w)));
}

__global__ __launch_bounds__(THREADS, 8)
void quant_pack_kernel(const float* __restrict__ x,
                       float* __restrict__ out_packed,
                       float* __restrict__ out_scales)
{
    const int t = threadIdx.x;
    const int row = blockIdx.x;
    const float4* __restrict__ xrow =
        reinterpret_cast<const float4*>(x + (size_t)row * H);

    // Streaming loads; keep all 16 floats in registers.
    float4 v0 = __ldcs(&xrow[2 * t]);
    float4 v1 = __ldcs(&xrow[2 * t + 1]);
    float4 v2 = __ldcs(&xrow[512 + 2 * t]);
    float4 v3 = __ldcs(&xrow[512 + 2 * t + 1]);

    float m = fmaxf(fmaxf(amax4(v0), amax4(v1)), fmaxf(amax4(v2), amax4(v3)));

    // Warp absmax, then cross-warp via shared + warp-0 shuffle reduce.
#pragma unroll
    for (int o = 16; o > 0; o >>= 1)
        m = fmaxf(m, __shfl_xor_sync(0xffffffffu, m, o));

    __shared__ float warpmax[THREADS / 32];
    __shared__ float s_inv;
    if ((t & 31) == 0) warpmax[t >> 5] = m;
    __syncthreads();
    if (t < 32) {
        float mm = (t < THREADS / 32) ? warpmax[t] : 0.0f;
#pragma unroll
        for (int o = 4; o > 0; o >>= 1)
            mm = fmaxf(mm, __shfl_xor_sync(0xffffffffu, mm, o));
        if (t == 0) {
            const float sc = mm / 7.0f;   // exact divide, once per row
            out_scales[row] = sc;
            s_inv = 1.0f / sc;            // exact reciprocal, once per row
        }
    }
    __syncthreads();
    const float inv = s_inv;

    // Two float4 (STG.128) streaming stores per thread.
    float4* __restrict__ orow =
        reinterpret_cast<float4*>(out_packed + (size_t)row * HP);
    float4 o0, o1;
    o0.x = pack2(v0.x, v0.y, inv);
    o0.y = pack2(v0.z, v0.w, inv);
    o0.z = pack2(v1.x, v1.y, inv);
    o0.w = pack2(v1.z, v1.w, inv);
    o1.x = pack2(v2.x, v2.y, inv);
    o1.y = pack2(v2.z, v2.w, inv);
    o1.z = pack2(v3.x, v3.y, inv);
    o1.w = pack2(v3.z, v3.w, inv);
    __stcs(&orow[t], o0);
    __stcs(&orow[256 + t], o1);
}

extern "C" void kernel_launch(void* const* d_in, const int* in_sizes, int n_in,
                              void* d_out, int out_size)
{
    const float* x = (const float*)d_in[0];
    const int N = in_sizes[0] / H;                   // 8192 rows

    float* out_packed = (float*)d_out;
    float* out_scales = (float*)d_out + (size_t)N * HP;

    quant_pack_kernel<<<N, THREADS>>>(x, out_packed, out_scales);
}

// round 15
// speedup vs baseline: 1.0374x; 1.0374x over previous
#include <cuda_runtime.h>
#include <cstdint>

// Quantizer: per-row symmetric int4 quant + nibble pack. x: [8192, 4096] fp32.
// Output = concat(packed, scales) upcast to fp32:
//   out[0 .. N*2048)       fp32 value of each packed signed byte
//   out[N*2048 .. +N)      fp32 per-row scale (absmax / 7)
//
// R14: converged compute structure (1 row/CTA, 256T, paired mapping, pure-FP
// pack) + BULK WRITE PATH: row output staged in SMEM, emitted as ONE 8KB
// cp.async.bulk (UBLKCP) per row instead of 64 interleaved 128B STG
// wavefronts — tests whether the mixed-stream HBM turnaround penalty is
// per-interleave-event (bulk helps) or pure byte-ratio (neutral).

#define H 4096
#define HP (H / 2)
#define THREADS 256

__device__ __forceinline__ float qclamp(float v, float inv) {
    return fmaxf(fminf(rintf(v * inv), 7.0f), -8.0f);
}

__device__ __forceinline__ float pack2(float a, float b, float inv) {
    const float q0 = qclamp(a, inv);                 // low nibble (even col)
    const float q1 = qclamp(b, inv);                 // high nibble (odd col)
    const float lo = (q0 < 0.0f) ? q0 + 16.0f : q0;  // q0 & 0xF as a value
    return fmaf(q1, 16.0f, lo);                      // signed byte value
}

__device__ __forceinline__ float amax4(float4 v) {
    return fmaxf(fmaxf(fabsf(v.x), fabsf(v.y)), fmaxf(fabsf(v.z), fabsf(v.w)));
}

__global__ __launch_bounds__(THREADS, 8)
void quant_pack_kernel(const float* __restrict__ x,
                       float* __restrict__ out_packed,
                       float* __restrict__ out_scales)
{
    const int t = threadIdx.x;
    const int row = blockIdx.x;
    const float4* __restrict__ xrow =
        reinterpret_cast<const float4*>(x + (size_t)row * H);

    __shared__ __align__(16) float stage[HP];        // 8KB row output staging
    __shared__ float warpmax[THREADS / 32];
    __shared__ float s_inv;

    // Streaming loads; keep all 16 floats in registers.
    float4 v0 = __ldcs(&xrow[2 * t]);
    float4 v1 = __ldcs(&xrow[2 * t + 1]);
    float4 v2 = __ldcs(&xrow[512 + 2 * t]);
    float4 v3 = __ldcs(&xrow[512 + 2 * t + 1]);

    float m = fmaxf(fmaxf(amax4(v0), amax4(v1)), fmaxf(amax4(v2), amax4(v3)));

#pragma unroll
    for (int o = 16; o > 0; o >>= 1)
        m = fmaxf(m, __shfl_xor_sync(0xffffffffu, m, o));

    if ((t & 31) == 0) warpmax[t >> 5] = m;
    __syncthreads();
    if (t < 32) {
        float mm = (t < THREADS / 32) ? warpmax[t] : 0.0f;
#pragma unroll
        for (int o = 4; o > 0; o >>= 1)
            mm = fmaxf(mm, __shfl_xor_sync(0xffffffffu, mm, o));
        if (t == 0) {
            const float sc = mm / 7.0f;   // exact divide, once per row
            out_scales[row] = sc;
            s_inv = 1.0f / sc;            // exact reciprocal, once per row
        }
    }
    __syncthreads();
    const float inv = s_inv;

    // Pack into SMEM staging (two STS.128 per thread).
    float4* stage4 = reinterpret_cast<float4*>(stage);
    float4 o0, o1;
    o0.x = pack2(v0.x, v0.y, inv);
    o0.y = pack2(v0.z, v0.w, inv);
    o0.z = pack2(v1.x, v1.y, inv);
    o0.w = pack2(v1.z, v1.w, inv);
    o1.x = pack2(v2.x, v2.y, inv);
    o1.y = pack2(v2.z, v2.w, inv);
    o1.z = pack2(v3.x, v3.y, inv);
    o1.w = pack2(v3.z, v3.w, inv);
    stage4[t] = o0;
    stage4[256 + t] = o1;
    __syncthreads();

    // One 8KB bulk store for the whole row's packed output.
    if (t == 0) {
        uint32_t s_addr;
        asm("{ .reg .u64 tmp; cvta.to.shared.u64 tmp, %1; cvt.u32.u64 %0, tmp; }"
            : "=r"(s_addr) : "l"(stage));
        asm volatile("fence.proxy.async.shared::cta;" ::: "memory");
        float* gdst = out_packed + (size_t)row * HP;
        asm volatile(
            "cp.async.bulk.global.shared::cta.bulk_group [%0], [%1], %2;"
            :: "l"(gdst), "r"(s_addr), "r"(HP * 4) : "memory");
        asm volatile("cp.async.bulk.commit_group;" ::: "memory");
        asm volatile("cp.async.bulk.wait_group.read 0;" ::: "memory");
    }
}

extern "C" void kernel_launch(void* const* d_in, const int* in_sizes, int n_in,
                              void* d_out, int out_size)
{
    const float* x = (const float*)d_in[0];
    const int N = in_sizes[0] / H;                   // 8192 rows

    float* out_packed = (float*)d_out;
    float* out_scales = (float*)d_out + (size_t)N * HP;

    quant_pack_kernel<<<N, THREADS>>>(x, out_packed, out_scales);
}